// round 14
// baseline (speedup 1.0000x reference)
#include <cuda_runtime.h>
#include <cstdint>

#define BATCH   64
#define QN      1000
#define CN      1203
#define NTOT    (QN * CN)          // 1203000 per batch
#define N4      (NTOT / 4)         // 300750 float4 per batch
#define ALL4    (BATCH * N4)       // 19248000 global float4
#define NCTA    444                // = 148 SMs * occ 3 : one balanced wave
#define PER     ((ALL4 + NCTA - 1) / NCTA)   // 43352 float4 per CTA
#define MAXSLOT 8                  // max contributors per batch
#define KTOP    100
#define KEEP    128
#define T1      512
#define TILE_F4 (2 * T1)           // 1024 float4 = 4096 floats per tile
#define BUF     8960               // 70KB shared candidate buffer
#define WATERMARK 640
// safety: barrier every 2 tiles; worst case 640 + 2*4096 = 8832 <= BUF

#define NEG_INF (-__int_as_float(0x7F800000))

typedef unsigned long long u64;

__device__ u64 g_cand[BATCH * MAXSLOT * KEEP];
__device__ int g_done[BATCH];      // zero-init; self-resetting per launch

// Reference sigmoid: XLA-GPU logistic -> 0.5 + 0.5*tanh.approx(0.5*x)
__device__ __forceinline__ float ref_sigmoid(float x) {
    float t;
    asm("tanh.approx.f32 %0, %1;" : "=f"(t) : "f"(x * 0.5f));
    return fmaf(0.5f, t, 0.5f);
}

__device__ __forceinline__ u64 packprob(float p, int idx) {
    return ((u64)__float_as_uint(p) << 32) | (unsigned)(~idx);
}
__device__ __forceinline__ u64 packlogit(float x, int idx) {
    unsigned bits = __float_as_uint(x);
    bits = (bits & 0x80000000u) ? ~bits : (bits | 0x80000000u);
    return ((u64)bits << 32) | (unsigned)(~idx);
}
__device__ __forceinline__ float ord2f(unsigned k) {
    unsigned x = (k & 0x80000000u) ? (k & 0x7FFFFFFFu) : ~k;
    return __uint_as_float(x);
}

// conservative logit guard: x <= guard => mufu_prob(x) < p (with margin)
__device__ __forceinline__ float guard_from_prob(float p) {
    float pf = p - 2e-3f;              // >= 3x mufu tanh abs-error bound
    if (pf <= 1e-7f) return NEG_INF;
    if (pf >= 1.0f - 1e-7f) pf = 1.0f - 1e-7f;
    return __logf(pf / (1.0f - pf)) - 2e-2f;
}

struct SelWS {
    int hist[256];
    int suff[257];
    int wsum[8];
    u64 sh_pref;
    u64 minkey;
    int sh_k;
    int flag;
    int sh_cnt;
};

// exact k-th largest u64 among s[0..n): MSD radix descent, plain-atomic
// histogram, early exit via min-scan. requires n >= k.
__device__ __noinline__ u64 radix_kth(const u64* s, int n, int k, SelWS* w, int tid) {
    const int lane = tid & 31;
    u64 prefix = 0, mask = 0;
    int kk = k;
    #pragma unroll 1
    for (int shift = 56; shift >= 0; shift -= 8) {
        if (tid < 256) w->hist[tid] = 0;
        if (tid == 0) w->flag = 0;
        __syncthreads();
        #pragma unroll 1
        for (int i = tid; i < n; i += T1) {
            u64 v = s[i];
            if ((v & mask) == prefix)
                atomicAdd(&w->hist[(int)((v >> shift) & 255)], 1);
        }
        __syncthreads();
        int ss = 0;
        if (tid < 256) {
            ss = w->hist[tid];
            #pragma unroll
            for (int o = 1; o < 32; o <<= 1) {
                int u = __shfl_down_sync(0xFFFFFFFFu, ss, o);
                if (lane + o < 32) ss += u;
            }
            if (lane == 0) w->wsum[tid >> 5] = ss;
        }
        __syncthreads();
        if (tid == 0) {
            int acc = 0;
            #pragma unroll
            for (int wi = 7; wi >= 0; --wi) { int t = w->wsum[wi]; w->wsum[wi] = acc; acc += t; }
            w->suff[256] = 0;
        }
        __syncthreads();
        if (tid < 256) w->suff[tid] = ss + w->wsum[tid >> 5];
        __syncthreads();
        if (tid < 256) {
            int GE = w->suff[tid], GT = w->suff[tid + 1];
            if (GT < kk && kk <= GE) {
                w->sh_k = kk - GT;
                w->sh_pref = prefix | ((u64)tid << shift);
                w->flag = ((kk - GT) == (GE - GT)) ? 1 : 0;
            }
        }
        __syncthreads();
        prefix = w->sh_pref;
        kk = w->sh_k;
        mask |= (0xFFull << shift);
        if (w->flag || shift == 0) {
            if (tid == 0) w->minkey = ~0ull;
            __syncthreads();
            u64 lm = ~0ull;
            #pragma unroll 1
            for (int i = tid; i < n; i += T1) {
                u64 v = s[i];
                if ((v & mask) == prefix) lm = min(lm, v);
            }
            #pragma unroll
            for (int o = 16; o > 0; o >>= 1)
                lm = min(lm, __shfl_down_sync(0xFFFFFFFFu, lm, o));
            if (lane == 0) atomicMin(&w->minkey, lm);
            __syncthreads();
            return w->minkey;
        }
        __syncthreads();
    }
    return prefix;
}

__device__ __forceinline__ void compact_ge(const u64* s, int n, u64 thr,
                                           u64* dst, int* sh_cnt, int tid) {
    if (tid == 0) *sh_cnt = 0;
    __syncthreads();
    #pragma unroll 1
    for (int i = tid; i < n; i += T1) {
        u64 v = s[i];
        if (v >= thr) dst[atomicAdd(sh_cnt, 1)] = v;
    }
    __syncthreads();
}

__device__ __forceinline__ void bitonic128(u64* s, int tid) {
    #pragma unroll 1
    for (int k = 2; k <= 128; k <<= 1) {
        #pragma unroll 1
        for (int j = k >> 1; j > 0; j >>= 1) {
            if (tid < 128) {
                int i = tid, ixj = i ^ j;
                if (ixj > i) {
                    u64 a = s[i], b = s[ixj];
                    if ((a < b) == ((i & k) == 0)) { s[i] = b; s[ixj] = a; }
                }
            }
            __syncthreads();
        }
    }
}

// per-thread collect + append for 2 float4
__device__ __forceinline__ void append_hits2(float4 a, float4 b, float g,
                                             int i0, int i1,
                                             u64* buf, int* cnt) {
    unsigned m = 0;
    if (a.x > g) m |= 1u;   if (a.y > g) m |= 2u;
    if (a.z > g) m |= 4u;   if (a.w > g) m |= 8u;
    if (b.x > g) m |= 16u;  if (b.y > g) m |= 32u;
    if (b.z > g) m |= 64u;  if (b.w > g) m |= 128u;
    if (m) {
        int pos = atomicAdd(cnt, __popc(m));
        const int x0 = i0 * 4, x1 = i1 * 4;
        if (m & 1u)   buf[pos++] = packprob(ref_sigmoid(a.x), x0 + 0);
        if (m & 2u)   buf[pos++] = packprob(ref_sigmoid(a.y), x0 + 1);
        if (m & 4u)   buf[pos++] = packprob(ref_sigmoid(a.z), x0 + 2);
        if (m & 8u)   buf[pos++] = packprob(ref_sigmoid(a.w), x0 + 3);
        if (m & 16u)  buf[pos++] = packprob(ref_sigmoid(b.x), x1 + 0);
        if (m & 32u)  buf[pos++] = packprob(ref_sigmoid(b.y), x1 + 1);
        if (m & 64u)  buf[pos++] = packprob(ref_sigmoid(b.z), x1 + 2);
        if (m & 128u) buf[pos++] = packprob(ref_sigmoid(b.w), x1 + 3);
    }
}

// stream [s,e) global float4 range; write exact top-KEEP (zero-padded) to dst
__device__ __noinline__ void process_segment(const float4* __restrict__ all4,
                                             int s, int e,
                                             u64* buf, u64* stage, SelWS* ws,
                                             int* cnt, float* guard_s,
                                             int tid, u64* dst) {
    const float4 NEG4 = make_float4(NEG_INF, NEG_INF, NEG_INF, NEG_INF);

    // first tile (bounds-checked) doubles as phase-A sample and tile-0 data
    const int i0 = s + tid, i1 = s + T1 + tid;
    float4 va = (i0 < e) ? __ldcs(all4 + i0) : NEG4;
    float4 vb = (i1 < e) ? __ldcs(all4 + i1) : NEG4;

    // Phase A: guard from top-KEEP of 512 thread-maxes
    {
        float mx = fmaxf(fmaxf(fmaxf(va.x, va.y), fmaxf(va.z, va.w)),
                         fmaxf(fmaxf(vb.x, vb.y), fmaxf(vb.z, vb.w)));
        buf[tid] = packlogit(mx, tid);
        __syncthreads();
        u64 kth = radix_kth(buf, T1, KEEP, ws, tid);
        if (tid == 0) {
            const float L = ord2f((unsigned)(kth >> 32));
            const float p = 1.0f / (1.0f + expf(-L));
            *guard_s = guard_from_prob(p);
            *cnt = 0;
        }
        __syncthreads();
    }

    const int span  = e - s;
    const int nfull = span / TILE_F4;

    #pragma unroll 1
    for (int t = 0; t < nfull; t++) {
        const int t0 = s + t * TILE_F4;
        const int nt0 = t0 + TILE_F4;

        // prefetch next tile before processing (in flight across the sync)
        float4 na = NEG4, nb = NEG4;
        if (t + 1 < nfull) {
            na = __ldcs(all4 + nt0 + tid);
            nb = __ldcs(all4 + nt0 + T1 + tid);
        } else {
            const int j0 = nt0 + tid, j1 = nt0 + T1 + tid;
            if (j0 < e) na = __ldcs(all4 + j0);
            if (j1 < e) nb = __ldcs(all4 + j1);
        }

        const float g = *guard_s;
        const float mx = fmaxf(fmaxf(fmaxf(va.x, va.y), fmaxf(va.z, va.w)),
                               fmaxf(fmaxf(vb.x, vb.y), fmaxf(vb.z, vb.w)));
        if (mx > g)
            append_hits2(va, vb, g, t0 + tid, t0 + T1 + tid, buf, cnt);

        if ((t & 1) || (t == nfull - 1)) {
            __syncthreads();
            if (*cnt > WATERMARK) {
                u64 kth = radix_kth(buf, *cnt, KEEP, ws, tid);
                compact_ge(buf, *cnt, kth, stage, &ws->sh_cnt, tid);
                for (int p = tid; p < KEEP; p += T1) buf[p] = stage[p];
                if (tid == 0) {
                    *cnt = KEEP;
                    *guard_s = guard_from_prob(__uint_as_float((unsigned)(kth >> 32)));
                }
                __syncthreads();
            }
        }
        va = na; vb = nb;
    }

    // tail tile (data already in registers, NEG_INF-padded)
    if (nfull * TILE_F4 < span) {
        const int t0 = s + nfull * TILE_F4;
        const float g = *guard_s;
        const float mx = fmaxf(fmaxf(fmaxf(va.x, va.y), fmaxf(va.z, va.w)),
                               fmaxf(fmaxf(vb.x, vb.y), fmaxf(vb.z, vb.w)));
        if (mx > g)
            append_hits2(va, vb, g, t0 + tid, t0 + T1 + tid, buf, cnt);
    }
    __syncthreads();

    // final exact top-KEEP (zero-padded if fewer) -> dst
    const int n = *cnt;
    if (n > KEEP) {
        u64 kth = radix_kth(buf, n, KEEP, ws, tid);
        compact_ge(buf, n, kth, stage, &ws->sh_cnt, tid);
        for (int p = tid; p < KEEP; p += T1) dst[p] = stage[p];
    } else {
        for (int p = tid; p < KEEP; p += T1) dst[p] = (p < n) ? buf[p] : 0ull;
    }
}

// merge all contributors of batch b and emit outputs
__device__ __noinline__ void merge_batch(int b, u64* buf, u64* stage, SelWS* ws,
                                         int tid,
                                         const float* __restrict__ bbox,
                                         const float* __restrict__ tsz,
                                         float* __restrict__ out) {
    const int f = (b * N4) / PER;
    const int l = ((b + 1) * N4 - 1) / PER;
    const int mn = (l - f + 1) * KEEP;            // <= 8*128 = 1024

    const u64* src = g_cand + (size_t)b * MAXSLOT * KEEP;
    for (int i = tid; i < mn; i += T1) buf[i] = src[i];
    __syncthreads();

    u64 kth = radix_kth(buf, mn, KTOP, ws, tid);
    compact_ge(buf, mn, kth, stage, &ws->sh_cnt, tid);
    for (int i = KTOP + tid; i < KEEP; i += T1) stage[i] = 0ull;
    __syncthreads();

    bitonic128(stage, tid);

    if (tid < KTOP) {
        const u64 cb = stage[tid];
        const float score = __uint_as_float((unsigned)(cb >> 32));
        const unsigned gidx = ~(unsigned)cb;
        const unsigned idx  = gidx - (unsigned)b * NTOT;   // local in batch

        const int q   = (int)(idx / CN);
        const int lab = (int)(idx % CN);

        const float4 bx = reinterpret_cast<const float4*>(bbox)[b * QN + q];
        const float ih = tsz[b * 2 + 0];
        const float iw = tsz[b * 2 + 1];

        out[b * KTOP + tid] = score;
        out[BATCH * KTOP + b * KTOP + tid] = (float)lab;
        float4 bo;
        bo.x = (bx.x - 0.5f * bx.z) * iw;
        bo.y = (bx.y - 0.5f * bx.w) * ih;
        bo.z = (bx.x + 0.5f * bx.z) * iw;
        bo.w = (bx.y + 0.5f * bx.w) * ih;
        reinterpret_cast<float4*>(out + 2 * BATCH * KTOP)[b * KTOP + tid] = bo;
    }
    __syncthreads();
}

// ---------------------------------------------------------------------------
// Fused kernel: 444 equal global slices, batch-segmented selection + merge
// out layout (float32): scores[B*K] | labels[B*K] | boxes[B*K*4]
// ---------------------------------------------------------------------------
__global__ __launch_bounds__(T1, 3)
void postproc_kernel(const float* __restrict__ logits,
                     const float* __restrict__ bbox,
                     const float* __restrict__ tsz,
                     float* __restrict__ out) {
    __shared__ u64 buf[BUF];
    __shared__ u64 stage[KEEP];
    __shared__ SelWS ws;
    __shared__ int cnt;
    __shared__ float guard_s;
    __shared__ int do0, do1;

    const int c   = blockIdx.x;
    const int tid = threadIdx.x;

    const float4* __restrict__ all4 = reinterpret_cast<const float4*>(logits);

    const int s = c * PER;
    const int e = min(s + PER, ALL4);
    const int b0 = s / N4;
    const int b1 = (e - 1) / N4;

    // segment 1 (batch b0)
    {
        const int e0 = (b0 == b1) ? e : (b0 + 1) * N4;
        const int slot0 = c - (b0 * N4) / PER;
        process_segment(all4, s, e0, buf, stage, &ws, &cnt, &guard_s, tid,
                        g_cand + ((size_t)b0 * MAXSLOT + slot0) * KEEP);
    }
    // segment 2 (batch b1, slot 0 by construction)
    if (b1 != b0) {
        const int e0 = (b0 + 1) * N4;
        process_segment(all4, e0, e, buf, stage, &ws, &cnt, &guard_s, tid,
                        g_cand + (size_t)b1 * MAXSLOT * KEEP);
    }

    // arrivals; last arriver merges its batch
    __threadfence();
    if (tid == 0) {
        {
            const int f = (b0 * N4) / PER, l = ((b0 + 1) * N4 - 1) / PER;
            const int expc = l - f + 1;
            int prev = atomicAdd(&g_done[b0], 1);
            do0 = (prev == expc - 1);
            if (do0) g_done[b0] = 0;          // self-reset for graph replays
        }
        do1 = 0;
        if (b1 != b0) {
            const int f = (b1 * N4) / PER, l = ((b1 + 1) * N4 - 1) / PER;
            const int expc = l - f + 1;
            int prev = atomicAdd(&g_done[b1], 1);
            do1 = (prev == expc - 1);
            if (do1) g_done[b1] = 0;
        }
    }
    __syncthreads();

    if (do0) { __threadfence(); merge_batch(b0, buf, stage, &ws, tid, bbox, tsz, out); }
    if (do1) { __threadfence(); merge_batch(b1, buf, stage, &ws, tid, bbox, tsz, out); }
}

extern "C" void kernel_launch(void* const* d_in, const int* in_sizes, int n_in,
                              void* d_out, int out_size) {
    const float* logits = (const float*)d_in[0];   // (64,1000,1203) f32
    const float* bbox   = (const float*)d_in[1];   // (64,1000,4)    f32
    const float* tsz    = (const float*)d_in[2];   // (64,2)         f32
    float* out          = (float*)d_out;           // 38400 f32

    postproc_kernel<<<NCTA, T1>>>(logits, bbox, tsz, out);
}

// round 15
// speedup vs baseline: 1.2947x; 1.2947x over previous
#include <cuda_runtime.h>
#include <cstdint>

#define BATCH   64
#define QN      1000
#define CN      1203
#define NTOT    (QN * CN)          // 1203000 per batch
#define N4      (NTOT / 4)         // 300750 float4 per batch
#define KTOP    100
#define KEEP    128                // survivors per chunk
#define CHUNKS  7
#define T1      512
#define VPT     2                  // float4 per thread per tile
#define TILE_F4 (VPT * T1)         // 1024 float4 = 4096 floats
#define BUF     8960               // 70KB shared candidate buffer
#define WATERMARK 640
// safety: sync every 2 tiles; worst case 640 + 2*4096 = 8832 <= BUF
#define MN      (CHUNKS * KEEP)    // 896 merge candidates per batch

#define NEG_INF (-__int_as_float(0x7F800000))

typedef unsigned long long u64;

__device__ u64 g_cand[BATCH * CHUNKS * KEEP];
__device__ int g_done[BATCH];      // zero-init; self-resetting per launch

// Reference sigmoid: XLA-GPU logistic -> 0.5 + 0.5*tanh.approx(0.5*x)
__device__ __forceinline__ float ref_sigmoid(float x) {
    float t;
    asm("tanh.approx.f32 %0, %1;" : "=f"(t) : "f"(x * 0.5f));
    return fmaf(0.5f, t, 0.5f);
}

__device__ __forceinline__ u64 packprob(float p, int idx) {
    return ((u64)__float_as_uint(p) << 32) | (unsigned)(~idx);
}
__device__ __forceinline__ u64 packlogit(float x, int idx) {
    unsigned bits = __float_as_uint(x);
    bits = (bits & 0x80000000u) ? ~bits : (bits | 0x80000000u);
    return ((u64)bits << 32) | (unsigned)(~idx);
}
__device__ __forceinline__ float ord2f(unsigned k) {
    unsigned x = (k & 0x80000000u) ? (k & 0x7FFFFFFFu) : ~k;
    return __uint_as_float(x);
}

// conservative logit guard: x <= guard => mufu_prob(x) < p (with margin)
__device__ __forceinline__ float guard_from_prob(float p) {
    float pf = p - 2e-3f;              // >= 3x mufu tanh abs-error bound
    if (pf <= 1e-7f) return NEG_INF;
    if (pf >= 1.0f - 1e-7f) pf = 1.0f - 1e-7f;
    return __logf(pf / (1.0f - pf)) - 2e-2f;
}

__device__ __forceinline__ void l2_prefetch(const float4* p) {
    asm volatile("prefetch.global.L2 [%0];" :: "l"(p));
}

struct SelWS {
    int hist[256];
    int suff[257];
    int wsum[8];
    u64 sh_pref;
    u64 minkey;
    int sh_k;
    int flag;
    int sh_cnt;
};

// exact k-th largest u64 among s[0..n): MSD radix descent, plain-atomic
// histogram, early exit via min-scan.
template <int NTHR>
__device__ u64 radix_kth(const u64* s, int n, int k, SelWS* w, int tid) {
    const int lane = tid & 31;
    u64 prefix = 0, mask = 0;
    int kk = k;
    #pragma unroll 1
    for (int shift = 56; shift >= 0; shift -= 8) {
        if (tid < 256) w->hist[tid] = 0;
        if (tid == 0) w->flag = 0;
        __syncthreads();
        #pragma unroll 1
        for (int i = tid; i < n; i += NTHR) {
            u64 v = s[i];
            if ((v & mask) == prefix)
                atomicAdd(&w->hist[(int)((v >> shift) & 255)], 1);
        }
        __syncthreads();
        int ss = 0;
        if (tid < 256) {
            ss = w->hist[tid];
            #pragma unroll
            for (int o = 1; o < 32; o <<= 1) {
                int u = __shfl_down_sync(0xFFFFFFFFu, ss, o);
                if (lane + o < 32) ss += u;
            }
            if (lane == 0) w->wsum[tid >> 5] = ss;
        }
        __syncthreads();
        if (tid == 0) {
            int acc = 0;
            #pragma unroll
            for (int wi = 7; wi >= 0; --wi) { int t = w->wsum[wi]; w->wsum[wi] = acc; acc += t; }
            w->suff[256] = 0;
        }
        __syncthreads();
        if (tid < 256) w->suff[tid] = ss + w->wsum[tid >> 5];
        __syncthreads();
        if (tid < 256) {
            int GE = w->suff[tid], GT = w->suff[tid + 1];
            if (GT < kk && kk <= GE) {
                w->sh_k = kk - GT;
                w->sh_pref = prefix | ((u64)tid << shift);
                w->flag = ((kk - GT) == (GE - GT)) ? 1 : 0;
            }
        }
        __syncthreads();
        prefix = w->sh_pref;
        kk = w->sh_k;
        mask |= (0xFFull << shift);
        if (w->flag || shift == 0) {
            if (tid == 0) w->minkey = ~0ull;
            __syncthreads();
            u64 lm = ~0ull;
            #pragma unroll 1
            for (int i = tid; i < n; i += NTHR) {
                u64 v = s[i];
                if ((v & mask) == prefix) lm = min(lm, v);
            }
            #pragma unroll
            for (int o = 16; o > 0; o >>= 1)
                lm = min(lm, __shfl_down_sync(0xFFFFFFFFu, lm, o));
            if (lane == 0) atomicMin(&w->minkey, lm);
            __syncthreads();
            return w->minkey;
        }
        __syncthreads();
    }
    return prefix;
}

template <int NTHR>
__device__ void compact_ge(const u64* s, int n, u64 thr, u64* dst,
                           int* sh_cnt, int tid) {
    if (tid == 0) *sh_cnt = 0;
    __syncthreads();
    #pragma unroll 1
    for (int i = tid; i < n; i += NTHR) {
        u64 v = s[i];
        if (v >= thr) dst[atomicAdd(sh_cnt, 1)] = v;
    }
    __syncthreads();
}

template <int NSORT, int NTHREADS>
__device__ __forceinline__ void bitonic_desc(u64* s, int tid) {
    #pragma unroll 1
    for (int k = 2; k <= NSORT; k <<= 1) {
        #pragma unroll 1
        for (int j = k >> 1; j > 0; j >>= 1) {
            for (int i = tid; i < NSORT; i += NTHREADS) {
                int ixj = i ^ j;
                if (ixj > i) {
                    u64 a = s[i], b = s[ixj];
                    if ((a < b) == ((i & k) == 0)) { s[i] = b; s[ixj] = a; }
                }
            }
            __syncthreads();
        }
    }
}

// per-thread collect + append for 2 float4 (explicit 8-way unroll)
__device__ __forceinline__ void append_hits2(float4 a, float4 b, float g,
                                             int i0, int i1,
                                             u64* buf, int* cnt) {
    unsigned m = 0;
    if (a.x > g) m |= 1u;   if (a.y > g) m |= 2u;
    if (a.z > g) m |= 4u;   if (a.w > g) m |= 8u;
    if (b.x > g) m |= 16u;  if (b.y > g) m |= 32u;
    if (b.z > g) m |= 64u;  if (b.w > g) m |= 128u;
    if (m) {
        int pos = atomicAdd(cnt, __popc(m));
        const int x0 = i0 * 4, x1 = i1 * 4;
        if (m & 1u)   buf[pos++] = packprob(ref_sigmoid(a.x), x0 + 0);
        if (m & 2u)   buf[pos++] = packprob(ref_sigmoid(a.y), x0 + 1);
        if (m & 4u)   buf[pos++] = packprob(ref_sigmoid(a.z), x0 + 2);
        if (m & 8u)   buf[pos++] = packprob(ref_sigmoid(a.w), x0 + 3);
        if (m & 16u)  buf[pos++] = packprob(ref_sigmoid(b.x), x1 + 0);
        if (m & 32u)  buf[pos++] = packprob(ref_sigmoid(b.y), x1 + 1);
        if (m & 64u)  buf[pos++] = packprob(ref_sigmoid(b.z), x1 + 2);
        if (m & 128u) buf[pos++] = packprob(ref_sigmoid(b.w), x1 + 3);
    }
}

// ---------------------------------------------------------------------------
// Fused kernel
// out layout (float32): scores[B*K] | labels[B*K] | boxes[B*K*4]
// ---------------------------------------------------------------------------
__global__ __launch_bounds__(T1, 3)
void postproc_kernel(const float* __restrict__ logits,
                     const float* __restrict__ bbox,
                     const float* __restrict__ tsz,
                     float* __restrict__ out) {
    __shared__ u64 buf[BUF];
    __shared__ u64 stage[KEEP];
    __shared__ SelWS ws;
    __shared__ int cnt;
    __shared__ float guard_s;
    __shared__ int merge_flag;

    const int b   = blockIdx.y;
    const int ch  = blockIdx.x;
    const int tid = threadIdx.x;

    const float4* __restrict__ base =
        reinterpret_cast<const float4*>(logits + (size_t)b * NTOT);

    const int per = (N4 + CHUNKS - 1) / CHUNKS;   // 42965
    const int lo  = ch * per;
    const int hi  = min(lo + per, N4);
    const int span  = hi - lo;
    const int nfull = span / TILE_F4;
    const float4 NEG4 = make_float4(NEG_INF, NEG_INF, NEG_INF, NEG_INF);

    // ---- Phase A: guard from top-KEEP of 512 thread-maxes of tile 0 ----
    {
        const int i0 = lo + tid, i1 = lo + T1 + tid;
        float4 a = (i0 < hi) ? __ldcs(base + i0) : NEG4;
        float4 c = (i1 < hi) ? __ldcs(base + i1) : NEG4;
        float mx = fmaxf(fmaxf(fmaxf(a.x, a.y), fmaxf(a.z, a.w)),
                         fmaxf(fmaxf(c.x, c.y), fmaxf(c.z, c.w)));
        buf[tid] = packlogit(mx, tid);
        __syncthreads();
        u64 kth = radix_kth<T1>(buf, T1, KEEP, &ws, tid);
        if (tid == 0) {
            const float L = ord2f((unsigned)(kth >> 32));
            const float p = 1.0f / (1.0f + expf(-L));   // accurate sigmoid
            guard_s = guard_from_prob(p);
            cnt = 0;
        }
        __syncthreads();
    }

    // ---- Phase B: prefetch-pipelined pass, barrier every 2nd tile,
    //      distance-2 L2 prefetch ----
    float4 va = NEG4, vb = NEG4;
    if (nfull > 0) {
        va = __ldcs(base + lo + tid);
        vb = __ldcs(base + lo + T1 + tid);
    }

    #pragma unroll 1
    for (int t = 0; t < nfull; t++) {
        const int t0 = lo + t * TILE_F4;
        const int nt0 = t0 + TILE_F4;

        // distance-2 L2 prefetch (register-free MLP; clamped in-range)
        {
            const int p0 = min(nt0 + TILE_F4 + tid, hi - 1);
            const int p1 = min(nt0 + TILE_F4 + T1 + tid, hi - 1);
            l2_prefetch(base + p0);
            l2_prefetch(base + p1);
        }

        // distance-1 register prefetch (in flight across the sync)
        float4 na = NEG4, nb = NEG4;
        if (t + 1 < nfull) {
            na = __ldcs(base + nt0 + tid);
            nb = __ldcs(base + nt0 + T1 + tid);
        } else {
            const int i0 = nt0 + tid, i1 = nt0 + T1 + tid;
            if (i0 < hi) na = __ldcs(base + i0);
            if (i1 < hi) nb = __ldcs(base + i1);
        }

        const float g = guard_s;
        const float mx = fmaxf(fmaxf(fmaxf(va.x, va.y), fmaxf(va.z, va.w)),
                               fmaxf(fmaxf(vb.x, vb.y), fmaxf(vb.z, vb.w)));
        if (mx > g)
            append_hits2(va, vb, g, t0 + tid, t0 + T1 + tid, buf, &cnt);

        // barrier + prune check only every 2nd tile (and on the last tile)
        if ((t & 1) || (t == nfull - 1)) {
            __syncthreads();
            if (cnt > WATERMARK) {
                u64 kth = radix_kth<T1>(buf, cnt, KEEP, &ws, tid);
                compact_ge<T1>(buf, cnt, kth, stage, &ws.sh_cnt, tid);
                for (int p = tid; p < KEEP; p += T1) buf[p] = stage[p];
                if (tid == 0) {
                    cnt     = KEEP;
                    guard_s = guard_from_prob(__uint_as_float((unsigned)(kth >> 32)));
                }
                __syncthreads();
            }
        }

        va = na; vb = nb;
    }

    // tail tile (data already prefetched, NEG_INF-padded)
    if (nfull * TILE_F4 < span) {
        const int t0 = lo + nfull * TILE_F4;
        const float g = guard_s;
        const float mx = fmaxf(fmaxf(fmaxf(va.x, va.y), fmaxf(va.z, va.w)),
                               fmaxf(fmaxf(vb.x, vb.y), fmaxf(vb.z, vb.w)));
        if (mx > g)
            append_hits2(va, vb, g, t0 + tid, t0 + T1 + tid, buf, &cnt);
    }
    __syncthreads();

    // ---- final exact top-KEEP of this chunk -> g_cand (unsorted) ----
    {
        const int n = cnt;
        u64 kth = radix_kth<T1>(buf, n, KEEP, &ws, tid);
        compact_ge<T1>(buf, n, kth, stage, &ws.sh_cnt, tid);
        u64* dst = g_cand + ((size_t)b * CHUNKS + ch) * KEEP;
        for (int p = tid; p < KEEP; p += T1) dst[p] = stage[p];
    }

    // ---- last CTA of this batch performs the merge ----
    __threadfence();
    if (tid == 0) {
        int prev = atomicAdd(&g_done[b], 1);
        merge_flag = (prev == CHUNKS - 1);
        if (merge_flag) g_done[b] = 0;        // self-reset for graph replays
    }
    __syncthreads();
    if (!merge_flag) return;
    __threadfence();

    const u64* src = g_cand + (size_t)b * MN;
    for (int i = tid; i < MN; i += T1) buf[i] = src[i];
    __syncthreads();

    u64 kth = radix_kth<T1>(buf, MN, KTOP, &ws, tid);
    compact_ge<T1>(buf, MN, kth, stage, &ws.sh_cnt, tid);
    for (int i = KTOP + tid; i < KEEP; i += T1) stage[i] = 0ull;
    __syncthreads();

    bitonic_desc<KEEP, T1>(stage, tid);

    if (tid < KTOP) {
        const u64 cb = stage[tid];
        const float score = __uint_as_float((unsigned)(cb >> 32));
        const unsigned idx = ~(unsigned)cb;

        const int q   = (int)(idx / CN);
        const int lab = (int)(idx % CN);

        const float4 bx = reinterpret_cast<const float4*>(bbox)[b * QN + q];
        const float ih = tsz[b * 2 + 0];
        const float iw = tsz[b * 2 + 1];

        out[b * KTOP + tid] = score;                        // scores
        out[BATCH * KTOP + b * KTOP + tid] = (float)lab;    // labels
        float4 bo;
        bo.x = (bx.x - 0.5f * bx.z) * iw;
        bo.y = (bx.y - 0.5f * bx.w) * ih;
        bo.z = (bx.x + 0.5f * bx.z) * iw;
        bo.w = (bx.y + 0.5f * bx.w) * ih;
        reinterpret_cast<float4*>(out + 2 * BATCH * KTOP)[b * KTOP + tid] = bo;
    }
}

extern "C" void kernel_launch(void* const* d_in, const int* in_sizes, int n_in,
                              void* d_out, int out_size) {
    const float* logits = (const float*)d_in[0];   // (64,1000,1203) f32
    const float* bbox   = (const float*)d_in[1];   // (64,1000,4)    f32
    const float* tsz    = (const float*)d_in[2];   // (64,2)         f32
    float* out          = (float*)d_out;           // 38400 f32

    dim3 grid(CHUNKS, BATCH);
    postproc_kernel<<<grid, T1>>>(logits, bbox, tsz, out);
}